// round 4
// baseline (speedup 1.0000x reference)
#include <cuda_runtime.h>
#include <math.h>

#define H 160           // B*G = 4*40 heads
#define C 13
#define T 1024
#define F 513           // rfft bins
#define NSIG (H * C)    // 2080 signals

// ---------------- scratch (device globals: allowed; no runtime alloc) ------
__device__ float2 d_W[512];        // twiddles exp(-2*pi*i*k/1024)
__device__ float2 d_X[H * C * F];  // spectrum, layout [head][c][f]
__device__ float2 d_Q[H * C * F];
__device__ float2 d_K[H * C * F];
__device__ float2 d_V[H * C * F];
__device__ float2 d_O[H * C * F];

// ---------------- twiddle init (double trig for precision) -----------------
__global__ void init_twiddles() {
    int k = threadIdx.x;  // 0..511
    double ang = -2.0 * 3.14159265358979323846 * (double)k / 1024.0;
    d_W[k] = make_float2((float)cos(ang), (float)sin(ang));
}

// ---------------- shared radix-2 DIT FFT core (1024 pts, 512 threads) ------
__device__ __forceinline__ void fft_stages(float2* a, bool inverse) {
    int tid = threadIdx.x;
#pragma unroll
    for (int s = 1; s <= 10; ++s) {
        __syncthreads();
        int half = 1 << (s - 1);
        int k = tid & (half - 1);
        int i0 = ((tid >> (s - 1)) << s) + k;
        float2 w = d_W[k << (10 - s)];
        if (inverse) w.y = -w.y;
        float2 u = a[i0];
        float2 v = a[i0 + half];
        float tr = w.x * v.x - w.y * v.y;
        float ti = w.x * v.y + w.y * v.x;
        a[i0]        = make_float2(u.x + tr, u.y + ti);
        a[i0 + half] = make_float2(u.x - tr, u.y - ti);
    }
    __syncthreads();
}

// ---------------- forward rfft: x[sig][0..1023] -> d_X[sig][0..512] --------
__global__ void fft_forward(const float* __restrict__ x) {
    __shared__ float2 a[1024];
    int sig = blockIdx.x;   // head*13 + c
    int tid = threadIdx.x;  // 0..511
    const float* xp = x + sig * 1024;
    a[__brev(tid) >> 22]       = make_float2(xp[tid], 0.f);
    a[__brev(tid + 512) >> 22] = make_float2(xp[tid + 512], 0.f);
    fft_stages(a, false);
    float2* Xp = d_X + sig * F;
    Xp[tid] = a[tid];
    if (tid == 0) Xp[512] = a[512];
}

// ---------------- QKV: [head][c][f] = sum_cin X[head][cin][f] * W[cin][c] --
__global__ void qkv_kernel(const float* __restrict__ wq,
                           const float* __restrict__ wk,
                           const float* __restrict__ wv) {
    __shared__ float ws[3][169];
    int tid = threadIdx.x;
    if (tid < 169) {
        ws[0][tid] = wq[tid];
        ws[1][tid] = wk[tid];
        ws[2][tid] = wv[tid];
    }
    __syncthreads();
    int head = blockIdx.y;
    int f = blockIdx.x * blockDim.x + tid;
    if (f >= F) return;
    float xr[13], xi[13];
#pragma unroll
    for (int c = 0; c < 13; ++c) {
        float2 v = d_X[(head * 13 + c) * F + f];
        xr[c] = v.x;
        xi[c] = v.y;
    }
#pragma unroll 1
    for (int co = 0; co < 13; ++co) {
        float qr = 0.f, qi = 0.f, kr = 0.f, ki = 0.f, vr = 0.f, vi = 0.f;
#pragma unroll
        for (int ci = 0; ci < 13; ++ci) {
            float a = ws[0][ci * 13 + co];
            qr = fmaf(xr[ci], a, qr); qi = fmaf(xi[ci], a, qi);
            float b = ws[1][ci * 13 + co];
            kr = fmaf(xr[ci], b, kr); ki = fmaf(xi[ci], b, ki);
            float g = ws[2][ci * 13 + co];
            vr = fmaf(xr[ci], g, vr); vi = fmaf(xi[ci], g, vi);
        }
        int o = (head * 13 + co) * F + f;
        d_Q[o] = make_float2(qr, qi);
        d_K[o] = make_float2(kr, ki);
        d_V[o] = make_float2(vr, vi);
    }
}

// ---------------- attention: 1 CTA = 16 rows of one head --------------------
// 256 threads = 8 warps, each warp owns 2 query rows (Q in registers).
// K/V tiles streamed through smem; each k/v column load serves BOTH rows.
#define TR 16
#define KT 128
#define NTILE 5  // ceil(513/128)

__global__ __launch_bounds__(256, 2) void attn_kernel() {
    __shared__ float2 q_sm[TR * 13];     // 1664 B
    __shared__ float  s_sm[TR * F];      // 32832 B
    __shared__ float2 kv_sm[13 * KT];    // 13312 B   (total 47808 B < 48 KB)

    int head = blockIdx.y;
    int tid = threadIdx.x, lane = tid & 31, w = tid >> 5;  // w = 0..7
    int r0 = 2 * w, r1 = 2 * w + 1;                         // local rows
    int f0 = blockIdx.x * TR + r0;
    int f1 = f0 + 1;
    bool act0 = f0 < F, act1 = f1 < F;

    // load Q tile into smem, then per-warp rows into registers
    for (int i = tid; i < TR * 13; i += 256) {
        int r = i / 13, c = i % 13;
        int fr = blockIdx.x * TR + r;
        q_sm[i] = (fr < F) ? d_Q[(head * 13 + c) * F + fr] : make_float2(0.f, 0.f);
    }
    __syncthreads();

    float2 q0[13], q1[13];
#pragma unroll
    for (int c = 0; c < 13; ++c) {
        q0[c] = q_sm[r0 * 13 + c];
        q1[c] = q_sm[r1 * 13 + c];
    }

    // pass 1: scores = |q . k^T|  (stream K tiles through smem)
    float m0 = -1e30f, m1 = -1e30f;
    for (int tile = 0; tile < NTILE; ++tile) {
        int base = tile * KT;
        __syncthreads();
        for (int i = tid; i < 13 * KT; i += 256) {
            int c = i / KT, fl = i % KT;
            int f2 = base + fl;
            kv_sm[i] = (f2 < F) ? d_K[(head * 13 + c) * F + f2] : make_float2(0.f, 0.f);
        }
        __syncthreads();
        for (int fl = lane; fl < KT; fl += 32) {
            int f2 = base + fl;
            if (f2 >= F) break;
            float2 k[13];
#pragma unroll
            for (int c = 0; c < 13; ++c) k[c] = kv_sm[c * KT + fl];
            float sr0 = 0.f, si0 = 0.f, sr1 = 0.f, si1 = 0.f;
#pragma unroll
            for (int c = 0; c < 13; ++c) {
                sr0 = fmaf(q0[c].x, k[c].x, sr0);
                sr0 = fmaf(-q0[c].y, k[c].y, sr0);
                si0 = fmaf(q0[c].x, k[c].y, si0);
                si0 = fmaf(q0[c].y, k[c].x, si0);
                sr1 = fmaf(q1[c].x, k[c].x, sr1);
                sr1 = fmaf(-q1[c].y, k[c].y, sr1);
                si1 = fmaf(q1[c].x, k[c].y, si1);
                si1 = fmaf(q1[c].y, k[c].x, si1);
            }
            float sc0 = sqrtf(sr0 * sr0 + si0 * si0);
            float sc1 = sqrtf(sr1 * sr1 + si1 * si1);
            s_sm[r0 * F + f2] = sc0;
            s_sm[r1 * F + f2] = sc1;
            m0 = fmaxf(m0, sc0);
            m1 = fmaxf(m1, sc1);
        }
    }

    // row softmax (per-warp: two rows, no cross-warp deps)
#pragma unroll
    for (int o = 16; o; o >>= 1) {
        m0 = fmaxf(m0, __shfl_xor_sync(0xffffffffu, m0, o));
        m1 = fmaxf(m1, __shfl_xor_sync(0xffffffffu, m1, o));
    }
    float l0 = 0.f, l1 = 0.f;
    for (int f2 = lane; f2 < F; f2 += 32) {
        float p0 = __expf(s_sm[r0 * F + f2] - m0);
        float p1 = __expf(s_sm[r1 * F + f2] - m1);
        s_sm[r0 * F + f2] = p0;
        s_sm[r1 * F + f2] = p1;
        l0 += p0;
        l1 += p1;
    }
#pragma unroll
    for (int o = 16; o; o >>= 1) {
        l0 += __shfl_xor_sync(0xffffffffu, l0, o);
        l1 += __shfl_xor_sync(0xffffffffu, l1, o);
    }
    float inv0 = 1.f / l0, inv1 = 1.f / l1;

    // pass 2: out = P @ V (stream V tiles; each v load serves both rows)
    float ar0[13], ai0[13], ar1[13], ai1[13];
#pragma unroll
    for (int c = 0; c < 13; ++c) { ar0[c] = ai0[c] = ar1[c] = ai1[c] = 0.f; }
    for (int tile = 0; tile < NTILE; ++tile) {
        int base = tile * KT;
        __syncthreads();
        for (int i = tid; i < 13 * KT; i += 256) {
            int c = i / KT, fl = i % KT;
            int f2 = base + fl;
            kv_sm[i] = (f2 < F) ? d_V[(head * 13 + c) * F + f2] : make_float2(0.f, 0.f);
        }
        __syncthreads();
        for (int fl = lane; fl < KT; fl += 32) {
            int f2 = base + fl;
            if (f2 >= F) break;
            float p0 = s_sm[r0 * F + f2];
            float p1 = s_sm[r1 * F + f2];
#pragma unroll
            for (int c = 0; c < 13; ++c) {
                float2 v = kv_sm[c * KT + fl];
                ar0[c] = fmaf(p0, v.x, ar0[c]);
                ai0[c] = fmaf(p0, v.y, ai0[c]);
                ar1[c] = fmaf(p1, v.x, ar1[c]);
                ai1[c] = fmaf(p1, v.y, ai1[c]);
            }
        }
    }

    // warp-reduce 13 complex accumulators per row, lane 0 writes
#pragma unroll
    for (int c = 0; c < 13; ++c) {
#pragma unroll
        for (int o = 16; o; o >>= 1) {
            ar0[c] += __shfl_xor_sync(0xffffffffu, ar0[c], o);
            ai0[c] += __shfl_xor_sync(0xffffffffu, ai0[c], o);
            ar1[c] += __shfl_xor_sync(0xffffffffu, ar1[c], o);
            ai1[c] += __shfl_xor_sync(0xffffffffu, ai1[c], o);
        }
    }
    if (lane == 0) {
#pragma unroll
        for (int c = 0; c < 13; ++c) {
            if (act0) d_O[(head * 13 + c) * F + f0] = make_float2(ar0[c] * inv0, ai0[c] * inv0);
            if (act1) d_O[(head * 13 + c) * F + f1] = make_float2(ar1[c] * inv1, ai1[c] * inv1);
        }
    }
}

// ---------------- irfft: Hermitian extend + inverse FFT, real part ---------
__global__ void ifft_kernel(float* __restrict__ out) {
    __shared__ float2 a[1024];
    int sig = blockIdx.x;
    int tid = threadIdx.x;  // 0..511
    const float2* Op = d_O + sig * F;
    float2 o = Op[tid];
    a[__brev(tid) >> 22] = o;
    if (tid > 0) a[__brev(1024 - tid) >> 22] = make_float2(o.x, -o.y);
    if (tid == 0) a[__brev(512) >> 22] = Op[512];
    fft_stages(a, true);
    const float scale = 1.0f / 1024.0f;
    float* op = out + sig * 1024;
    op[tid]       = a[tid].x * scale;
    op[tid + 512] = a[tid + 512].x * scale;
}

// ---------------- launcher --------------------------------------------------
extern "C" void kernel_launch(void* const* d_in, const int* in_sizes, int n_in,
                              void* d_out, int out_size) {
    const float* x  = (const float*)d_in[0];
    const float* wq = (const float*)d_in[1];
    const float* wk = (const float*)d_in[2];
    const float* wv = (const float*)d_in[3];
    float* out = (float*)d_out;

    init_twiddles<<<1, 512>>>();
    fft_forward<<<NSIG, 512>>>(x);
    qkv_kernel<<<dim3(3, H), 256>>>(wq, wk, wv);
    attn_kernel<<<dim3((F + TR - 1) / TR, H), 256>>>();
    ifft_kernel<<<NSIG, 512>>>(out);
}

// round 5
// speedup vs baseline: 1.1290x; 1.1290x over previous
#include <cuda_runtime.h>
#include <math.h>

#define H 160           // B*G = 4*40 heads
#define C 13
#define T 1024
#define F 513           // rfft bins
#define NSIG (H * C)    // 2080 signals

typedef unsigned long long ull;

// ---------------- f32x2 packed math helpers (sm_103a FFMA2) ----------------
__device__ __forceinline__ ull pk2(float a, float b) {
    ull r;
    asm("mov.b64 %0, {%1, %2};" : "=l"(r) : "r"(__float_as_uint(a)), "r"(__float_as_uint(b)));
    return r;
}
__device__ __forceinline__ void upk2(ull v, float& a, float& b) {
    unsigned lo, hi;
    asm("mov.b64 {%0, %1}, %2;" : "=r"(lo), "=r"(hi) : "l"(v));
    a = __uint_as_float(lo);
    b = __uint_as_float(hi);
}
__device__ __forceinline__ ull fma2(ull a, ull b, ull c) {
    ull d;
    asm("fma.rn.f32x2 %0, %1, %2, %3;" : "=l"(d) : "l"(a), "l"(b), "l"(c));
    return d;
}

// ---------------- scratch (device globals: allowed; no runtime alloc) ------
__device__ float2 d_W[512];        // twiddles exp(-2*pi*i*k/1024)
__device__ float2 d_X[H * C * F];  // spectrum, layout [head][c][f]
__device__ float2 d_Q[H * C * F];
__device__ float2 d_K[H * C * F];
__device__ float2 d_V[H * C * F];
__device__ float2 d_O[H * C * F];

// ---------------- twiddle init (double trig for precision) -----------------
__global__ void init_twiddles() {
    int k = threadIdx.x;  // 0..511
    double ang = -2.0 * 3.14159265358979323846 * (double)k / 1024.0;
    d_W[k] = make_float2((float)cos(ang), (float)sin(ang));
}

// ---------------- shared radix-2 DIT FFT core (1024 pts, 512 threads) ------
__device__ __forceinline__ void fft_stages(float2* a, bool inverse) {
    int tid = threadIdx.x;
#pragma unroll
    for (int s = 1; s <= 10; ++s) {
        __syncthreads();
        int half = 1 << (s - 1);
        int k = tid & (half - 1);
        int i0 = ((tid >> (s - 1)) << s) + k;
        float2 w = d_W[k << (10 - s)];
        if (inverse) w.y = -w.y;
        float2 u = a[i0];
        float2 v = a[i0 + half];
        float tr = w.x * v.x - w.y * v.y;
        float ti = w.x * v.y + w.y * v.x;
        a[i0]        = make_float2(u.x + tr, u.y + ti);
        a[i0 + half] = make_float2(u.x - tr, u.y - ti);
    }
    __syncthreads();
}

// ---------------- forward rfft: x[sig][0..1023] -> d_X[sig][0..512] --------
__global__ void fft_forward(const float* __restrict__ x) {
    __shared__ float2 a[1024];
    int sig = blockIdx.x;   // head*13 + c
    int tid = threadIdx.x;  // 0..511
    const float* xp = x + sig * 1024;
    a[__brev(tid) >> 22]       = make_float2(xp[tid], 0.f);
    a[__brev(tid + 512) >> 22] = make_float2(xp[tid + 512], 0.f);
    fft_stages(a, false);
    float2* Xp = d_X + sig * F;
    Xp[tid] = a[tid];
    if (tid == 0) Xp[512] = a[512];
}

// ---------------- QKV: [head][c][f] = sum_cin X[head][cin][f] * W[cin][c] --
__global__ void qkv_kernel(const float* __restrict__ wq,
                           const float* __restrict__ wk,
                           const float* __restrict__ wv) {
    __shared__ float ws[3][169];
    int tid = threadIdx.x;
    if (tid < 169) {
        ws[0][tid] = wq[tid];
        ws[1][tid] = wk[tid];
        ws[2][tid] = wv[tid];
    }
    __syncthreads();
    int head = blockIdx.y;
    int f = blockIdx.x * blockDim.x + tid;
    if (f >= F) return;
    float xr[13], xi[13];
#pragma unroll
    for (int c = 0; c < 13; ++c) {
        float2 v = d_X[(head * 13 + c) * F + f];
        xr[c] = v.x;
        xi[c] = v.y;
    }
#pragma unroll 1
    for (int co = 0; co < 13; ++co) {
        float qr = 0.f, qi = 0.f, kr = 0.f, ki = 0.f, vr = 0.f, vi = 0.f;
#pragma unroll
        for (int ci = 0; ci < 13; ++ci) {
            float a = ws[0][ci * 13 + co];
            qr = fmaf(xr[ci], a, qr); qi = fmaf(xi[ci], a, qi);
            float b = ws[1][ci * 13 + co];
            kr = fmaf(xr[ci], b, kr); ki = fmaf(xi[ci], b, ki);
            float g = ws[2][ci * 13 + co];
            vr = fmaf(xr[ci], g, vr); vi = fmaf(xi[ci], g, vi);
        }
        int o = (head * 13 + co) * F + f;
        d_Q[o] = make_float2(qr, qi);
        d_K[o] = make_float2(kr, ki);
        d_V[o] = make_float2(vr, vi);
    }
}

// ---------------- attention ------------------------------------------------
// 256 threads = 8 warps; each warp owns a ROW PAIR (2 query rows), packed
// into f32x2 registers. Pass 1 uses FFMA2 (4 FMA2 + 4 dup-MOV per c vs 8
// scalar FFMA) spreading work across fma+alu pipes. Scores stored packed
// {row0,row1} so softmax + pass 2 read single LDS.64. Pass 2 scalar (dup
// cost there exceeds FMA savings).
#define TR 16
#define KT 128
#define NTILE 5

__global__ __launch_bounds__(256, 3) void attn_kernel() {
    __shared__ float2 s_sm[8 * F];       // packed scores per warp-row-pair: 32832 B
    __shared__ float2 kv_sm[13 * KT];    // 13312 B   (total 46144 B)

    int head = blockIdx.y;
    int tid = threadIdx.x, lane = tid & 31, w = tid >> 5;  // w = 0..7
    int f0 = blockIdx.x * TR + 2 * w;
    int f1 = f0 + 1;
    bool act0 = f0 < F, act1 = f1 < F;

    // Q row pair -> packed registers (warp-uniform broadcast loads)
    ull qx[13], qy[13];
#pragma unroll
    for (int c = 0; c < 13; ++c) {
        float2 a = act0 ? d_Q[(head * 13 + c) * F + f0] : make_float2(0.f, 0.f);
        float2 b = act1 ? d_Q[(head * 13 + c) * F + f1] : make_float2(0.f, 0.f);
        qx[c] = pk2(a.x, b.x);
        qy[c] = pk2(a.y, b.y);
    }

    // pass 1: scores = |q . conj? no: q . k with complex mul| ; sr = A - B
    float m0 = 0.f, m1 = 0.f;  // scores are non-negative
    const ull Z = pk2(0.f, 0.f);
    for (int tile = 0; tile < NTILE; ++tile) {
        int base = tile * KT;
        __syncthreads();
        for (int i = tid; i < 13 * KT; i += 256) {
            int c = i >> 7, fl = i & 127;
            int f2 = base + fl;
            kv_sm[c * KT + fl] = (f2 < F) ? d_K[(head * 13 + c) * F + f2] : make_float2(0.f, 0.f);
        }
        __syncthreads();
#pragma unroll
        for (int j = 0; j < 4; ++j) {
            int fl = j * 32 + lane;
            int f2 = base + fl;
            ull A = Z, B = Z, S = Z;
#pragma unroll
            for (int c = 0; c < 13; ++c) {
                float2 k = kv_sm[c * KT + fl];
                ull kxx = pk2(k.x, k.x);
                ull kyy = pk2(k.y, k.y);
                A = fma2(qx[c], kxx, A);   // += qx*kx   (-> sr pos part)
                B = fma2(qy[c], kyy, B);   // += qy*ky   (-> sr neg part)
                S = fma2(qx[c], kyy, S);   // += qx*ky   (-> si)
                S = fma2(qy[c], kxx, S);   // += qy*kx
            }
            float a0, a1, b0, b1, s0, s1;
            upk2(A, a0, a1); upk2(B, b0, b1); upk2(S, s0, s1);
            float sr0 = a0 - b0, sr1 = a1 - b1;
            float n0 = fmaf(sr0, sr0, s0 * s0);
            float n1 = fmaf(sr1, sr1, s1 * s1);
            float sc0 = n0 > 0.f ? n0 * __frsqrt_rn(n0) : 0.f;
            float sc1 = n1 > 0.f ? n1 * __frsqrt_rn(n1) : 0.f;
            m0 = fmaxf(m0, sc0);
            m1 = fmaxf(m1, sc1);
            if (f2 < F) s_sm[w * F + f2] = make_float2(sc0, sc1);
        }
    }

    // row-pair softmax (per warp)
#pragma unroll
    for (int o = 16; o; o >>= 1) {
        m0 = fmaxf(m0, __shfl_xor_sync(0xffffffffu, m0, o));
        m1 = fmaxf(m1, __shfl_xor_sync(0xffffffffu, m1, o));
    }
    float l0 = 0.f, l1 = 0.f;
    for (int f2 = lane; f2 < F; f2 += 32) {
        float2 s = s_sm[w * F + f2];
        float p0 = __expf(s.x - m0);
        float p1 = __expf(s.y - m1);
        s_sm[w * F + f2] = make_float2(p0, p1);
        l0 += p0;
        l1 += p1;
    }
#pragma unroll
    for (int o = 16; o; o >>= 1) {
        l0 += __shfl_xor_sync(0xffffffffu, l0, o);
        l1 += __shfl_xor_sync(0xffffffffu, l1, o);
    }
    float inv0 = 1.f / l0, inv1 = 1.f / l1;

    // pass 2: out = P @ V (scalar; one V load serves both rows)
    float ar0[13], ai0[13], ar1[13], ai1[13];
#pragma unroll
    for (int c = 0; c < 13; ++c) { ar0[c] = ai0[c] = ar1[c] = ai1[c] = 0.f; }
    for (int tile = 0; tile < NTILE; ++tile) {
        int base = tile * KT;
        __syncthreads();
        for (int i = tid; i < 13 * KT; i += 256) {
            int c = i >> 7, fl = i & 127;
            int f2 = base + fl;
            kv_sm[c * KT + fl] = (f2 < F) ? d_V[(head * 13 + c) * F + f2] : make_float2(0.f, 0.f);
        }
        __syncthreads();
#pragma unroll
        for (int j = 0; j < 4; ++j) {
            int fl = j * 32 + lane;
            int f2 = base + fl;
            float2 p = (f2 < F) ? s_sm[w * F + f2] : make_float2(0.f, 0.f);
#pragma unroll
            for (int c = 0; c < 13; ++c) {
                float2 v = kv_sm[c * KT + fl];
                ar0[c] = fmaf(p.x, v.x, ar0[c]);
                ai0[c] = fmaf(p.x, v.y, ai0[c]);
                ar1[c] = fmaf(p.y, v.x, ar1[c]);
                ai1[c] = fmaf(p.y, v.y, ai1[c]);
            }
        }
    }

    // warp-reduce accumulators, lane 0 writes
#pragma unroll
    for (int c = 0; c < 13; ++c) {
#pragma unroll
        for (int o = 16; o; o >>= 1) {
            ar0[c] += __shfl_xor_sync(0xffffffffu, ar0[c], o);
            ai0[c] += __shfl_xor_sync(0xffffffffu, ai0[c], o);
            ar1[c] += __shfl_xor_sync(0xffffffffu, ar1[c], o);
            ai1[c] += __shfl_xor_sync(0xffffffffu, ai1[c], o);
        }
    }
    if (lane == 0) {
#pragma unroll
        for (int c = 0; c < 13; ++c) {
            if (act0) d_O[(head * 13 + c) * F + f0] = make_float2(ar0[c] * inv0, ai0[c] * inv0);
            if (act1) d_O[(head * 13 + c) * F + f1] = make_float2(ar1[c] * inv1, ai1[c] * inv1);
        }
    }
}

// ---------------- irfft: Hermitian extend + inverse FFT, real part ---------
__global__ void ifft_kernel(float* __restrict__ out) {
    __shared__ float2 a[1024];
    int sig = blockIdx.x;
    int tid = threadIdx.x;  // 0..511
    const float2* Op = d_O + sig * F;
    float2 o = Op[tid];
    a[__brev(tid) >> 22] = o;
    if (tid > 0) a[__brev(1024 - tid) >> 22] = make_float2(o.x, -o.y);
    if (tid == 0) a[__brev(512) >> 22] = Op[512];
    fft_stages(a, true);
    const float scale = 1.0f / 1024.0f;
    float* op = out + sig * 1024;
    op[tid]       = a[tid].x * scale;
    op[tid + 512] = a[tid + 512].x * scale;
}

// ---------------- launcher --------------------------------------------------
extern "C" void kernel_launch(void* const* d_in, const int* in_sizes, int n_in,
                              void* d_out, int out_size) {
    const float* x  = (const float*)d_in[0];
    const float* wq = (const float*)d_in[1];
    const float* wk = (const float*)d_in[2];
    const float* wv = (const float*)d_in[3];
    float* out = (float*)d_out;

    init_twiddles<<<1, 512>>>();
    fft_forward<<<NSIG, 512>>>(x);
    qkv_kernel<<<dim3(3, H), 256>>>(wq, wk, wv);
    attn_kernel<<<dim3((F + TR - 1) / TR, H), 256>>>();
    ifft_kernel<<<NSIG, 512>>>(out);
}